// round 2
// baseline (speedup 1.0000x reference)
#include <cuda_runtime.h>

// Fused transformer block, fp32, f32x2-packed FMAs.
// B=8192, T=8, C=512, H=8, HS=64, FF=2048. G=2 batches per CTA.

#define Cd 512
#define Td 8
#define Hd 8
#define HSd 64
#define FFd 2048
#define Gd 2
#define ROWS 16          // Gd*Td
#define XS 20            // padded transposed-activation stride (floats)
#define NT 256

// smem layout (floats)
#define OFF_X    0          // 16x512           = 8192
#define OFF_XN   8192       // 512 x XS         = 10240 (transposed LN out)
#define OFF_P    18432      // 16x512
#define OFF_K    26624      // 16x512
#define OFF_V    34816      // 16x512
#define OFF_WEI  43008      // 16x64
#define OFF_SAT  26624      // reuse K+V region: 512 x XS = 10240
#define SMEM_FLOATS 44032
#define SMEM_BYTES  (SMEM_FLOATS * 4)

typedef unsigned long long ull;

__device__ __forceinline__ ull pack2(float a, float b) {
    ull r; asm("mov.b64 %0, {%1, %2};" : "=l"(r) : "f"(a), "f"(b)); return r;
}
__device__ __forceinline__ void ffma2(ull &d, ull a, ull b) {
    asm("fma.rn.f32x2 %0, %1, %2, %0;" : "+l"(d) : "l"(a), "l"(b));
}
__device__ __forceinline__ float2 unpack2(ull v) {
    float2 r; asm("mov.b64 {%0, %1}, %2;" : "=f"(r.x), "=f"(r.y) : "l"(v)); return r;
}
__device__ __forceinline__ float wsum(float v) {
    #pragma unroll
    for (int m = 16; m > 0; m >>= 1) v += __shfl_xor_sync(0xffffffffu, v, m);
    return v;
}

__global__ void __launch_bounds__(NT, 1)
block_kernel(const float* __restrict__ gidx,
             const float* __restrict__ lg1, const float* __restrict__ lb1,
             const float* __restrict__ lg2, const float* __restrict__ lb2,
             const float* __restrict__ Wp, const float* __restrict__ bp,
             const float* __restrict__ Wk, const float* __restrict__ bk,
             const float* __restrict__ Wv, const float* __restrict__ bv,
             const float* __restrict__ W1, const float* __restrict__ b1f,
             const float* __restrict__ W2, const float* __restrict__ b2f,
             float* __restrict__ gout)
{
    extern __shared__ float smem[];
    float* sx   = smem + OFF_X;
    float* sxn  = smem + OFF_XN;
    float* sp   = smem + OFF_P;
    float* sk   = smem + OFF_K;
    float* sv   = smem + OFF_V;
    float* swei = smem + OFF_WEI;
    float* sat  = smem + OFF_SAT;

    const int tid  = threadIdx.x;
    const int lane = tid & 31;
    const int w    = tid >> 5;
    const long long base = (long long)blockIdx.x * (ROWS * Cd);

    // ---- load idx tile (16 x 512) ----
    {
        const float4* gx = (const float4*)(gidx + base);
        float4* sx4 = (float4*)sx;
        #pragma unroll
        for (int i = 0; i < 8; i++) sx4[tid + i * NT] = gx[tid + i * NT];
    }
    __syncthreads();

    // ---- LN1: warp w handles rows 2w, 2w+1; write transposed sxn[c][r] ----
    #pragma unroll
    for (int rr = 0; rr < 2; rr++) {
        int r = w * 2 + rr;
        const float* xr = sx + r * Cd;
        float s1 = 0.f, s2 = 0.f;
        #pragma unroll
        for (int c = lane; c < Cd; c += 32) { float v = xr[c]; s1 += v; s2 += v * v; }
        s1 = wsum(s1); s2 = wsum(s2);
        float mean = s1 * (1.0f / Cd);
        float var  = s2 * (1.0f / Cd) - mean * mean;
        float rstd = rsqrtf(var + 1e-5f);
        #pragma unroll
        for (int c = lane; c < Cd; c += 32)
            sxn[c * XS + r] = (xr[c] - mean) * rstd * lg1[c] + lb1[c];
    }
    __syncthreads();

    // ---- QKV projections: column-stationary, 2 cols/thread, rows packed f32x2 ----
    {
        const int j0 = tid, j1 = tid + NT;
        #pragma unroll
        for (int m = 0; m < 3; m++) {
            const float* Wm = (m == 0) ? Wp : (m == 1) ? Wk : Wv;
            const float* bm = (m == 0) ? bp : (m == 1) ? bk : bv;
            float* dst      = (m == 0) ? sp : (m == 1) ? sk : sv;
            const float* w0 = Wm + (j0 >> 6) * (Cd * HSd) + (j0 & 63);
            const float* w1 = Wm + (j1 >> 6) * (Cd * HSd) + (j1 & 63);
            ull a0[8], a1[8];
            #pragma unroll
            for (int i = 0; i < 8; i++) { a0[i] = 0ull; a1[i] = 0ull; }
            #pragma unroll 4
            for (int c = 0; c < Cd; c++) {
                float wa = w0[c * HSd];
                float wb = w1[c * HSd];
                ull pa = pack2(wa, wa), pb = pack2(wb, wb);
                const ulonglong2* xq = (const ulonglong2*)(sxn + c * XS);
                ulonglong2 q0 = xq[0], q1 = xq[1], q2 = xq[2], q3 = xq[3];
                ull xr[8] = {q0.x, q0.y, q1.x, q1.y, q2.x, q2.y, q3.x, q3.y};
                #pragma unroll
                for (int i = 0; i < 8; i++) { ffma2(a0[i], xr[i], pa); ffma2(a1[i], xr[i], pb); }
            }
            float bj0 = bm[j0], bj1 = bm[j1];
            #pragma unroll
            for (int i = 0; i < 8; i++) {
                float2 v0 = unpack2(a0[i]), v1 = unpack2(a1[i]);
                dst[(2 * i)     * Cd + j0] = v0.x + bj0;
                dst[(2 * i + 1) * Cd + j0] = v0.y + bj0;
                dst[(2 * i)     * Cd + j1] = v1.x + bj1;
                dst[(2 * i + 1) * Cd + j1] = v1.y + bj1;
            }
        }
    }
    __syncthreads();

    // ---- attention: warp w handles tasks 2w, 2w+1; task = (g,h) ----
    // phase A: logits + causal softmax -> swei (two half-passes: 64 entries, 32 lanes)
    #pragma unroll
    for (int u = 0; u < 2; u++) {
        int tk = w * 2 + u;
        int g = tk >> 3, h = tk & 7;
        #pragma unroll
        for (int half = 0; half < 2; half++) {
            int idx = lane + half * 32;
            int t = idx >> 3, s = idx & 7;
            const float4* pr = (const float4*)(sp + (g * 8 + t) * Cd + h * HSd);
            const float4* kr = (const float4*)(sk + (g * 8 + s) * Cd + h * HSd);
            float acc = 0.f;
            #pragma unroll
            for (int i = 0; i < 16; i++) {
                float4 a = pr[i], b = kr[i];
                acc += a.x * b.x + a.y * b.y + a.z * b.z + a.w * b.w;
            }
            float logit = acc * 0.125f;               // 1/sqrt(64)
            bool valid  = (s <= t);
            float ml = valid ? logit : -3.0e38f;
            float mx = ml;
            mx = fmaxf(mx, __shfl_xor_sync(0xffffffffu, mx, 1));
            mx = fmaxf(mx, __shfl_xor_sync(0xffffffffu, mx, 2));
            mx = fmaxf(mx, __shfl_xor_sync(0xffffffffu, mx, 4));
            float e = valid ? __expf(logit - mx) : 0.f;
            float sm = e;
            sm += __shfl_xor_sync(0xffffffffu, sm, 1);
            sm += __shfl_xor_sync(0xffffffffu, sm, 2);
            sm += __shfl_xor_sync(0xffffffffu, sm, 4);
            swei[tk * 64 + idx] = e / sm;
        }
    }
    __syncthreads();
    // phase B: att = wei @ v, overwrite sp
    #pragma unroll
    for (int u = 0; u < 2; u++) {
        int tk = w * 2 + u;
        int g = tk >> 3, h = tk & 7;
        int d0 = lane, d1 = lane + 32;
        #pragma unroll
        for (int t = 0; t < 8; t++) {
            float a0 = 0.f, a1 = 0.f;
            #pragma unroll
            for (int s = 0; s < 8; s++) {
                float wv = swei[tk * 64 + t * 8 + s];
                const float* vr = sv + (g * 8 + s) * Cd + h * HSd;
                a0 += wv * vr[d0];
                a1 += wv * vr[d1];
            }
            sp[(g * 8 + t) * Cd + h * HSd + d0] = a0;
            sp[(g * 8 + t) * Cd + h * HSd + d1] = a1;
        }
    }
    __syncthreads();

    // ---- LN2 over (att + x), write transposed into sxn ----
    #pragma unroll
    for (int rr = 0; rr < 2; rr++) {
        int r = w * 2 + rr;
        const float* ar = sp + r * Cd;
        const float* xr = sx + r * Cd;
        float s1 = 0.f, s2 = 0.f;
        #pragma unroll
        for (int c = lane; c < Cd; c += 32) { float v = ar[c] + xr[c]; s1 += v; s2 += v * v; }
        s1 = wsum(s1); s2 = wsum(s2);
        float mean = s1 * (1.0f / Cd);
        float var  = s2 * (1.0f / Cd) - mean * mean;
        float rstd = rsqrtf(var + 1e-5f);
        #pragma unroll
        for (int c = lane; c < Cd; c += 32)
            sxn[c * XS + r] = (ar[c] + xr[c] - mean) * rstd * lg2[c] + lb2[c];
    }
    __syncthreads();

    // ---- FFN: 4 chunks of 512 FF-cols; output accumulated in registers ----
    const int c0 = tid, c1 = tid + NT;
    ull ob0[8], ob1[8];
    #pragma unroll
    for (int i = 0; i < 8; i++) { ob0[i] = 0ull; ob1[i] = 0ull; }

    for (int ch = 0; ch < 4; ch++) {
        const int fb = ch * 512;
        // a-phase: a[r][f] = relu(h @ W1 + b1) for 2 f-cols/thread
        {
            const int f0 = fb + tid, f1 = fb + tid + NT;
            ull a0[8], a1[8];
            #pragma unroll
            for (int i = 0; i < 8; i++) { a0[i] = 0ull; a1[i] = 0ull; }
            #pragma unroll 4
            for (int c = 0; c < Cd; c++) {
                float wa = W1[c * FFd + f0];
                float wb = W1[c * FFd + f1];
                ull pa = pack2(wa, wa), pb = pack2(wb, wb);
                const ulonglong2* xq = (const ulonglong2*)(sxn + c * XS);
                ulonglong2 q0 = xq[0], q1 = xq[1], q2 = xq[2], q3 = xq[3];
                ull xr[8] = {q0.x, q0.y, q1.x, q1.y, q2.x, q2.y, q3.x, q3.y};
                #pragma unroll
                for (int i = 0; i < 8; i++) { ffma2(a0[i], xr[i], pa); ffma2(a1[i], xr[i], pb); }
            }
            float ba = b1f[f0], bb = b1f[f1];
            #pragma unroll
            for (int i = 0; i < 8; i++) {
                float2 v0 = unpack2(a0[i]), v1 = unpack2(a1[i]);
                sat[tid        * XS + 2 * i]     = fmaxf(v0.x + ba, 0.f);
                sat[tid        * XS + 2 * i + 1] = fmaxf(v0.y + ba, 0.f);
                sat[(tid + NT) * XS + 2 * i]     = fmaxf(v1.x + bb, 0.f);
                sat[(tid + NT) * XS + 2 * i + 1] = fmaxf(v1.y + bb, 0.f);
            }
        }
        __syncthreads();
        // b-phase: out += a @ W2 for 2 c-cols/thread
        {
            #pragma unroll 4
            for (int fl = 0; fl < 512; fl++) {
                const int f = fb + fl;
                float wa = W2[f * Cd + c0];
                float wb = W2[f * Cd + c1];
                ull pa = pack2(wa, wa), pb = pack2(wb, wb);
                const ulonglong2* aq = (const ulonglong2*)(sat + fl * XS);
                ulonglong2 q0 = aq[0], q1 = aq[1], q2 = aq[2], q3 = aq[3];
                ull xr[8] = {q0.x, q0.y, q1.x, q1.y, q2.x, q2.y, q3.x, q3.y};
                #pragma unroll
                for (int i = 0; i < 8; i++) { ffma2(ob0[i], xr[i], pa); ffma2(ob1[i], xr[i], pb); }
            }
        }
        __syncthreads();
    }

    // ---- epilogue: out = ffn + b2 + idx (original residual) ----
    {
        float bc0 = b2f[c0], bc1 = b2f[c1];
        float* go = gout + base;
        #pragma unroll
        for (int i = 0; i < 8; i++) {
            float2 v0 = unpack2(ob0[i]), v1 = unpack2(ob1[i]);
            int r0 = 2 * i, r1 = 2 * i + 1;
            go[r0 * Cd + c0] = v0.x + bc0 + sx[r0 * Cd + c0];
            go[r1 * Cd + c0] = v0.y + bc0 + sx[r1 * Cd + c0];
            go[r0 * Cd + c1] = v1.x + bc1 + sx[r0 * Cd + c1];
            go[r1 * Cd + c1] = v1.y + bc1 + sx[r1 * Cd + c1];
        }
    }
}

extern "C" void kernel_launch(void* const* d_in, const int* in_sizes, int n_in,
                              void* d_out, int out_size)
{
    (void)in_sizes; (void)n_in; (void)out_size;
    cudaFuncSetAttribute(block_kernel, cudaFuncAttributeMaxDynamicSharedMemorySize, SMEM_BYTES);
    block_kernel<<<4096, NT, SMEM_BYTES>>>(
        (const float*)d_in[0],
        (const float*)d_in[1], (const float*)d_in[2],
        (const float*)d_in[3], (const float*)d_in[4],
        (const float*)d_in[5], (const float*)d_in[6],
        (const float*)d_in[7], (const float*)d_in[8],
        (const float*)d_in[9], (const float*)d_in[10],
        (const float*)d_in[11], (const float*)d_in[12],
        (const float*)d_in[13], (const float*)d_in[14],
        (float*)d_out);
}

// round 3
// speedup vs baseline: 1.2200x; 1.2200x over previous
#include <cuda_runtime.h>

// Fused transformer block, fp32, f32x2-packed FMAs, 512 threads / 1 col per thread.
// B=8192, T=8, C=512, H=8, HS=64, FF=2048. G=2 batches per CTA (16 rows).

#define Cd 512
#define Td 8
#define Hd 8
#define HSd 64
#define FFd 2048
#define ROWS 16
#define XS 20            // padded transposed-activation stride (floats)
#define NT 512

// smem layout (floats)
#define OFF_X    0          // 16x512           = 8192
#define OFF_XN   8192       // 512 x XS         = 10240 (transposed LN out)
#define OFF_P    18432      // 16x512
#define OFF_K    26624      // 16x512
#define OFF_V    34816      // 16x512
#define OFF_WEI  43008      // 16x64
#define OFF_SAT  26624      // reuse K+V region: 512 x XS = 10240
#define SMEM_FLOATS 44032
#define SMEM_BYTES  (SMEM_FLOATS * 4)

typedef unsigned long long ull;

__device__ __forceinline__ ull pack2(float a, float b) {
    ull r; asm("mov.b64 %0, {%1, %2};" : "=l"(r) : "f"(a), "f"(b)); return r;
}
__device__ __forceinline__ void ffma2(ull &d, ull a, ull b) {
    asm("fma.rn.f32x2 %0, %1, %2, %0;" : "+l"(d) : "l"(a), "l"(b));
}
__device__ __forceinline__ float2 unpack2(ull v) {
    float2 r; asm("mov.b64 {%0, %1}, %2;" : "=f"(r.x), "=f"(r.y) : "l"(v)); return r;
}
__device__ __forceinline__ float wsum(float v) {
    #pragma unroll
    for (int m = 16; m > 0; m >>= 1) v += __shfl_xor_sync(0xffffffffu, v, m);
    return v;
}

__global__ void __launch_bounds__(NT, 1)
block_kernel(const float* __restrict__ gidx,
             const float* __restrict__ lg1, const float* __restrict__ lb1,
             const float* __restrict__ lg2, const float* __restrict__ lb2,
             const float* __restrict__ Wp, const float* __restrict__ bp,
             const float* __restrict__ Wk, const float* __restrict__ bk,
             const float* __restrict__ Wv, const float* __restrict__ bv,
             const float* __restrict__ W1, const float* __restrict__ b1f,
             const float* __restrict__ W2, const float* __restrict__ b2f,
             float* __restrict__ gout)
{
    extern __shared__ float smem[];
    float* sx   = smem + OFF_X;
    float* sxn  = smem + OFF_XN;
    float* sp   = smem + OFF_P;
    float* sk   = smem + OFF_K;
    float* sv   = smem + OFF_V;
    float* swei = smem + OFF_WEI;
    float* sat  = smem + OFF_SAT;

    const int tid  = threadIdx.x;
    const int lane = tid & 31;
    const int w    = tid >> 5;          // 0..15
    const long long base = (long long)blockIdx.x * (ROWS * Cd);

    // ---- load idx tile (16 x 512) ----
    {
        const float4* gx = (const float4*)(gidx + base);
        float4* sx4 = (float4*)sx;
        #pragma unroll
        for (int i = 0; i < 4; i++) sx4[tid + i * NT] = gx[tid + i * NT];
    }
    __syncthreads();

    // ---- LN1: warp w handles row w; write transposed sxn[c][r] ----
    {
        int r = w;
        const float* xr = sx + r * Cd;
        float s1 = 0.f, s2 = 0.f;
        #pragma unroll
        for (int c = lane; c < Cd; c += 32) { float v = xr[c]; s1 += v; s2 += v * v; }
        s1 = wsum(s1); s2 = wsum(s2);
        float mean = s1 * (1.0f / Cd);
        float var  = s2 * (1.0f / Cd) - mean * mean;
        float rstd = rsqrtf(var + 1e-5f);
        #pragma unroll
        for (int c = lane; c < Cd; c += 32)
            sxn[c * XS + r] = (xr[c] - mean) * rstd * lg1[c] + lb1[c];
    }
    __syncthreads();

    // ---- QKV projections: merged k-loop, 1 col/thread, 24 FFMA2 per c ----
    {
        const int j = tid;
        const int hoff = (j >> 6) * (Cd * HSd) + (j & 63);
        const float* wpp = Wp + hoff;
        const float* wkp = Wk + hoff;
        const float* wvp = Wv + hoff;
        ull ap[8], ak[8], av[8];
        #pragma unroll
        for (int i = 0; i < 8; i++) { ap[i] = 0ull; ak[i] = 0ull; av[i] = 0ull; }
        #pragma unroll 4
        for (int c = 0; c < Cd; c++) {
            float fp = wpp[c * HSd];
            float fk = wkp[c * HSd];
            float fv = wvp[c * HSd];
            ull pp = pack2(fp, fp), pk = pack2(fk, fk), pv = pack2(fv, fv);
            const ulonglong2* xq = (const ulonglong2*)(sxn + c * XS);
            ulonglong2 q0 = xq[0], q1 = xq[1], q2 = xq[2], q3 = xq[3];
            ull xr[8] = {q0.x, q0.y, q1.x, q1.y, q2.x, q2.y, q3.x, q3.y};
            #pragma unroll
            for (int i = 0; i < 8; i++) {
                ffma2(ap[i], xr[i], pp);
                ffma2(ak[i], xr[i], pk);
                ffma2(av[i], xr[i], pv);
            }
        }
        float bjp = bp[j], bjk = bk[j], bjv = bv[j];
        #pragma unroll
        for (int i = 0; i < 8; i++) {
            float2 vp = unpack2(ap[i]), vk = unpack2(ak[i]), vv = unpack2(av[i]);
            sp[(2 * i)     * Cd + j] = vp.x + bjp;
            sp[(2 * i + 1) * Cd + j] = vp.y + bjp;
            sk[(2 * i)     * Cd + j] = vk.x + bjk;
            sk[(2 * i + 1) * Cd + j] = vk.y + bjk;
            sv[(2 * i)     * Cd + j] = vv.x + bjv;
            sv[(2 * i + 1) * Cd + j] = vv.y + bjv;
        }
    }
    __syncthreads();

    // ---- attention: warp w handles task w = (g,h) ----
    // phase A: logits + causal softmax -> swei (two half-passes of 32 entries)
    {
        int tk = w;
        int g = tk >> 3, h = tk & 7;
        #pragma unroll
        for (int half = 0; half < 2; half++) {
            int idx = lane + half * 32;
            int t = idx >> 3, s = idx & 7;
            const float4* pr = (const float4*)(sp + (g * 8 + t) * Cd + h * HSd);
            const float4* kr = (const float4*)(sk + (g * 8 + s) * Cd + h * HSd);
            float acc = 0.f;
            #pragma unroll
            for (int i = 0; i < 16; i++) {
                float4 a = pr[i], b = kr[i];
                acc += a.x * b.x + a.y * b.y + a.z * b.z + a.w * b.w;
            }
            float logit = acc * 0.125f;               // 1/sqrt(64)
            bool valid  = (s <= t);
            float ml = valid ? logit : -3.0e38f;
            float mx = ml;
            mx = fmaxf(mx, __shfl_xor_sync(0xffffffffu, mx, 1));
            mx = fmaxf(mx, __shfl_xor_sync(0xffffffffu, mx, 2));
            mx = fmaxf(mx, __shfl_xor_sync(0xffffffffu, mx, 4));
            float e = valid ? __expf(logit - mx) : 0.f;
            float sm = e;
            sm += __shfl_xor_sync(0xffffffffu, sm, 1);
            sm += __shfl_xor_sync(0xffffffffu, sm, 2);
            sm += __shfl_xor_sync(0xffffffffu, sm, 4);
            swei[tk * 64 + idx] = e / sm;
        }
    }
    __syncthreads();
    // phase B: att = wei @ v, overwrite sp
    {
        int tk = w;
        int g = tk >> 3, h = tk & 7;
        int d0 = lane, d1 = lane + 32;
        #pragma unroll
        for (int t = 0; t < 8; t++) {
            float a0 = 0.f, a1 = 0.f;
            #pragma unroll
            for (int s = 0; s < 8; s++) {
                float wv = swei[tk * 64 + t * 8 + s];
                const float* vr = sv + (g * 8 + s) * Cd + h * HSd;
                a0 += wv * vr[d0];
                a1 += wv * vr[d1];
            }
            sp[(g * 8 + t) * Cd + h * HSd + d0] = a0;
            sp[(g * 8 + t) * Cd + h * HSd + d1] = a1;
        }
    }
    __syncthreads();

    // ---- LN2 over (att + x), write transposed into sxn ----
    {
        int r = w;
        const float* ar = sp + r * Cd;
        const float* xr = sx + r * Cd;
        float s1 = 0.f, s2 = 0.f;
        #pragma unroll
        for (int c = lane; c < Cd; c += 32) { float v = ar[c] + xr[c]; s1 += v; s2 += v * v; }
        s1 = wsum(s1); s2 = wsum(s2);
        float mean = s1 * (1.0f / Cd);
        float var  = s2 * (1.0f / Cd) - mean * mean;
        float rstd = rsqrtf(var + 1e-5f);
        #pragma unroll
        for (int c = lane; c < Cd; c += 32)
            sxn[c * XS + r] = (ar[c] + xr[c] - mean) * rstd * lg2[c] + lb2[c];
    }
    __syncthreads();

    // ---- FFN: 4 chunks of 512 FF-cols; 1 col/thread; output accum in regs ----
    ull ob[8];
    #pragma unroll
    for (int i = 0; i < 8; i++) ob[i] = 0ull;

    for (int ch = 0; ch < 4; ch++) {
        const int fb = ch * 512;
        // a-phase: a[r][f] = relu(h @ W1 + b1), f = fb + tid
        {
            const int f = fb + tid;
            ull a0[8];
            #pragma unroll
            for (int i = 0; i < 8; i++) a0[i] = 0ull;
            #pragma unroll 4
            for (int c = 0; c < Cd; c++) {
                float wa = W1[c * FFd + f];
                ull pa = pack2(wa, wa);
                const ulonglong2* xq = (const ulonglong2*)(sxn + c * XS);
                ulonglong2 q0 = xq[0], q1 = xq[1], q2 = xq[2], q3 = xq[3];
                ull xr[8] = {q0.x, q0.y, q1.x, q1.y, q2.x, q2.y, q3.x, q3.y};
                #pragma unroll
                for (int i = 0; i < 8; i++) ffma2(a0[i], xr[i], pa);
            }
            float ba = b1f[f];
            #pragma unroll
            for (int i = 0; i < 8; i++) {
                float2 v0 = unpack2(a0[i]);
                sat[tid * XS + 2 * i]     = fmaxf(v0.x + ba, 0.f);
                sat[tid * XS + 2 * i + 1] = fmaxf(v0.y + ba, 0.f);
            }
        }
        __syncthreads();
        // b-phase: out += a @ W2, out col = tid
        {
            #pragma unroll 4
            for (int fl = 0; fl < 512; fl++) {
                float wa = W2[(fb + fl) * Cd + tid];
                ull pa = pack2(wa, wa);
                const ulonglong2* aq = (const ulonglong2*)(sat + fl * XS);
                ulonglong2 q0 = aq[0], q1 = aq[1], q2 = aq[2], q3 = aq[3];
                ull xr[8] = {q0.x, q0.y, q1.x, q1.y, q2.x, q2.y, q3.x, q3.y};
                #pragma unroll
                for (int i = 0; i < 8; i++) ffma2(ob[i], xr[i], pa);
            }
        }
        __syncthreads();
    }

    // ---- epilogue: out = ffn + b2 + idx (original residual) ----
    {
        float bc = b2f[tid];
        float* go = gout + base;
        #pragma unroll
        for (int i = 0; i < 8; i++) {
            float2 v0 = unpack2(ob[i]);
            int r0 = 2 * i, r1 = 2 * i + 1;
            go[r0 * Cd + tid] = v0.x + bc + sx[r0 * Cd + tid];
            go[r1 * Cd + tid] = v0.y + bc + sx[r1 * Cd + tid];
        }
    }
}

extern "C" void kernel_launch(void* const* d_in, const int* in_sizes, int n_in,
                              void* d_out, int out_size)
{
    (void)in_sizes; (void)n_in; (void)out_size;
    cudaFuncSetAttribute(block_kernel, cudaFuncAttributeMaxDynamicSharedMemorySize, SMEM_BYTES);
    block_kernel<<<4096, NT, SMEM_BYTES>>>(
        (const float*)d_in[0],
        (const float*)d_in[1], (const float*)d_in[2],
        (const float*)d_in[3], (const float*)d_in[4],
        (const float*)d_in[5], (const float*)d_in[6],
        (const float*)d_in[7], (const float*)d_in[8],
        (const float*)d_in[9], (const float*)d_in[10],
        (const float*)d_in[11], (const float*)d_in[12],
        (const float*)d_in[13], (const float*)d_in[14],
        (float*)d_out);
}